// round 2
// baseline (speedup 1.0000x reference)
#include <cuda_runtime.h>
#include <math.h>

#define NP 2048
#define NBLK_B 293   // passB blocks: 293 * 7 >= 2048

// Scratch (max-sized for level 2: C=100, Q=20)
__device__ __align__(16) float g_T0[16*100*16];
__device__ __align__(16) float g_WS1[16*100*16];
__device__ __align__(16) float g_R[16*20*100];
__device__ __align__(16) float g_HQ[16*20*100*16];
__device__ __align__(16) float g_HdotO[16*20*100];
__device__ __align__(16) float g_out0[16*100*16];
__device__ __align__(16) float g_WS1part[NBLK_B * 16*100*16];  // ~30 MB

__device__ __forceinline__ float dot8(float4 w0, float4 w1, float4 xa, float4 xb) {
    return w0.x*xa.x + w0.y*xa.y + w0.z*xa.z + w0.w*xa.w
         + w1.x*xb.x + w1.y*xb.y + w1.z*xb.z + w1.w*xb.w;
}

__device__ __forceinline__ float sigmoidf(float x) {
    return 1.f / (1.f + __expf(-x));
}

__global__ void k_zero() {
    int i = blockIdx.x*256 + threadIdx.x;
    if (i < 16*100*16) g_T0[i] = 0.f;
    if (i < 16*20*100) g_R[i] = 0.f;
}

// HQ[b,q,c,d] = sum_e Wh[q,c,d,e] * prev[b,q,e]
__global__ void k_hq(const float* __restrict__ Wh, const float* __restrict__ prev,
                     int Q, int C) {
    int idx = blockIdx.x*256 + threadIdx.x;
    if (idx >= 16*Q*C*16) return;
    int d   = idx & 15;
    int rem = idx >> 4;          // (b*Q+q)*C + c
    int c   = rem % C;
    int bq  = rem / C;           // b*Q + q
    const float4* wh = (const float4*)(Wh + ((size_t)(((bq % Q)*C + c)*16 + d))*16);
    const float4* pv = (const float4*)(prev + (size_t)bq*16);
    float s = 0.f;
    #pragma unroll
    for (int e4 = 0; e4 < 4; ++e4) {
        float4 w = wh[e4], x = pv[e4];
        s += w.x*x.x + w.y*x.y + w.z*x.z + w.w*x.w;
    }
    g_HQ[idx] = s;
}

// T0[b,c,d] += sum_{p in chunk, i} W[p,c,d,i] * X[b,p,i]
__global__ void k_passA(const float* __restrict__ W, const float* __restrict__ X, int C) {
    int CD = C*16;
    int cd = blockIdx.x*128 + threadIdx.x;
    if (cd >= CD) return;
    int pBeg = blockIdx.y*128;
    float acc[16];
    #pragma unroll
    for (int b = 0; b < 16; ++b) acc[b] = 0.f;
    for (int p = pBeg; p < pBeg+128; ++p) {
        const float4* wp = (const float4*)(W + (size_t)p*CD*8 + (size_t)cd*8);
        float4 w0 = wp[0], w1 = wp[1];
        #pragma unroll
        for (int b = 0; b < 16; ++b) {
            const float4* xp = (const float4*)(X + ((size_t)b*NP + p)*8);
            acc[b] += dot8(w0, w1, xp[0], xp[1]);
        }
    }
    #pragma unroll
    for (int b = 0; b < 16; ++b) atomicAdd(&g_T0[b*CD + cd], acc[b]);
}

// out0[b,c,:] = squash( (a*T0 + (1-a)*rep*sum_q HQ) / C )
__global__ void k_ws0(const float* __restrict__ alpha, int C, int Q, int rep, int h) {
    int bc = blockIdx.x*256 + threadIdx.x;
    if (bc >= 16*C) return;
    int b = bc / C, c = bc % C;
    float a = 1.f, oma = 0.f;
    if (h) { a = sigmoidf(alpha[0]); oma = 1.f - a; }
    float invC = 1.f / (float)C;
    float v[16]; float sq = 0.f;
    #pragma unroll
    for (int d = 0; d < 16; ++d) {
        float t = a * g_T0[(b*C + c)*16 + d];
        if (h) {
            float hs = 0.f;
            for (int q = 0; q < Q; ++q) hs += g_HQ[((b*Q + q)*C + c)*16 + d];
            t += oma * (float)rep * hs;
        }
        t *= invC;
        v[d] = t; sq += t*t;
    }
    float sc = (sq/(1.f+sq)) * rsqrtf(sq + 1e-7f);
    #pragma unroll
    for (int d = 0; d < 16; ++d) g_out0[(b*C + c)*16 + d] = v[d]*sc;
}

// HdotO[b,q,c] = sum_d HQ[b,q,c,d] * out0[b,c,d]
__global__ void k_hdoto(int Q, int C) {
    int idx = blockIdx.x*256 + threadIdx.x;
    if (idx >= 16*Q*C) return;
    int c = idx % C;
    int b = (idx / C) / Q;
    const float* hq = g_HQ + (size_t)idx*16;
    const float* o  = g_out0 + (size_t)(b*C + c)*16;
    float s = 0.f;
    #pragma unroll
    for (int d = 0; d < 16; ++d) s += hq[d]*o[d];
    g_HdotO[idx] = s;
}

// Routing iteration 1: raw -> softmax -> ws1 partial (a-part in smem, hq-part via R atomics)
__global__ void __launch_bounds__(256)
k_passB(const float* __restrict__ W, const float* __restrict__ X,
        const float* __restrict__ alpha, int C, int Q, int repQ, int h) {
    extern __shared__ float sm[];
    float* ws1s = sm;               // 16*C*16
    float* rawS = sm + 16*C*16;     // 16*C
    int t = threadIdx.x;
    float a = 1.f, oma = 0.f;
    if (h) { a = sigmoidf(alpha[0]); oma = 1.f - a; }
    int tot = 16*C*16;
    for (int i = t; i < tot; i += 256) ws1s[i] = 0.f;
    __syncthreads();
    int b = t & 15, cB = t >> 4;
    int pBeg = blockIdx.x*7;
    int pEnd = min(pBeg+7, NP);
    for (int p = pBeg; p < pEnd; ++p) {
        const float4* xp = (const float4*)(X + ((size_t)b*NP + p)*8);
        float4 xa = xp[0], xb = xp[1];
        int q = h ? (p % Q) : 0;
        bool hv = h && (p < repQ);
        const float* Wp = W + (size_t)p*C*128;
        // phase 1: raw[b,c] = a * <predW, out0> + (1-a)*HdotO
        for (int c = cB; c < C; c += 16) {
            const float4* wc = (const float4*)(Wp + (size_t)c*128);
            const float4* ob = (const float4*)(g_out0 + (size_t)(b*C + c)*16);
            float r = 0.f;
            #pragma unroll
            for (int d4 = 0; d4 < 4; ++d4) {
                float pw0 = dot8(wc[d4*8+0], wc[d4*8+1], xa, xb);
                float pw1 = dot8(wc[d4*8+2], wc[d4*8+3], xa, xb);
                float pw2 = dot8(wc[d4*8+4], wc[d4*8+5], xa, xb);
                float pw3 = dot8(wc[d4*8+6], wc[d4*8+7], xa, xb);
                float4 o = ob[d4];
                r += pw0*o.x + pw1*o.y + pw2*o.z + pw3*o.w;
            }
            r *= a;
            if (hv) r += oma * g_HdotO[(size_t)(b*Q + q)*C + c];
            rawS[b*C + c] = r;
        }
        __syncthreads();
        // phase 2: softmax over c, 16 lanes per b-row
        {
            int bS = t >> 4, j = t & 15;
            float m = -1e30f;
            for (int c = j; c < C; c += 16) m = fmaxf(m, rawS[bS*C + c]);
            #pragma unroll
            for (int k = 8; k; k >>= 1) m = fmaxf(m, __shfl_xor_sync(0xffffffffu, m, k));
            float s = 0.f;
            for (int c = j; c < C; c += 16) {
                float e = __expf(rawS[bS*C + c] - m);
                rawS[bS*C + c] = e; s += e;
            }
            #pragma unroll
            for (int k = 8; k; k >>= 1) s += __shfl_xor_sync(0xffffffffu, s, k);
            float inv = 1.f / s;
            for (int c = j; c < C; c += 16) rawS[bS*C + c] *= inv;
        }
        __syncthreads();
        // phase 3: ws1 += a*rw*predW ; R += rw
        for (int c = cB; c < C; c += 16) {
            float rw  = rawS[b*C + c];
            float arw = a * rw;
            const float4* wc = (const float4*)(Wp + (size_t)c*128);
            float* wsb = ws1s + (size_t)(b*C + c)*16;
            #pragma unroll
            for (int d = 0; d < 16; ++d) {
                float pw = dot8(wc[d*2], wc[d*2+1], xa, xb);
                wsb[d] += arw * pw;
            }
            if (hv) atomicAdd(&g_R[(size_t)(b*Q + q)*C + c], rw);
        }
        __syncthreads();
    }
    // non-atomic per-block partial flush (coalesced)
    float* part = g_WS1part + (size_t)blockIdx.x * tot;
    for (int i = t; i < tot; i += 256) part[i] = ws1s[i];
}

// WS1[i] = sum_k part[k][i]  (coalesced tree reduce over NBLK_B partials)
__global__ void k_reduce(int C) {
    int tot = 16*C*16;
    int i = blockIdx.x*256 + threadIdx.x;
    if (i >= tot) return;
    float s = 0.f;
    for (int k = 0; k < NBLK_B; ++k) s += g_WS1part[(size_t)k*tot + i];
    g_WS1[i] = s;
}

// out[b,c,:] = squash( WS1 + (1-a)*sum_q R[b,q,c]*HQ[b,q,c,:] )
__global__ void k_final(const float* __restrict__ alpha, int C, int Q, int h,
                        float* __restrict__ outp) {
    int bc = blockIdx.x*256 + threadIdx.x;
    if (bc >= 16*C) return;
    int b = bc / C, c = bc % C;
    float a = 1.f, oma = 0.f;
    if (h) { a = sigmoidf(alpha[0]); oma = 1.f - a; }
    float v[16]; float sq = 0.f;
    #pragma unroll
    for (int d = 0; d < 16; ++d) {
        float t = g_WS1[(b*C + c)*16 + d];
        if (h) {
            float hs = 0.f;
            for (int q = 0; q < Q; ++q)
                hs += g_R[(b*Q + q)*C + c] * g_HQ[((b*Q + q)*C + c)*16 + d];
            t += oma * hs;
        }
        v[d] = t; sq += t*t;
    }
    float sc = (sq/(1.f+sq)) * rsqrtf(sq + 1e-7f);
    #pragma unroll
    for (int d = 0; d < 16; ++d) outp[(b*C + c)*16 + d] = v[d]*sc;
}

extern "C" void kernel_launch(void* const* d_in, const int* in_sizes, int n_in,
                              void* d_out, int out_size) {
    // Resolve inputs by element count (all distinct except the two alphas -> in order)
    const float *X=0,*W0=0,*W1=0,*W2=0,*Wh1=0,*Wh2=0,*al1=0,*al2=0;
    for (int i = 0; i < n_in; ++i) {
        const float* pp = (const float*)d_in[i];
        switch (in_sizes[i]) {
            case 16*2048*8:      X   = pp; break;   // 262144
            case 2048*2*16*8:    W0  = pp; break;   // 524288
            case 2048*20*16*8:   W1  = pp; break;   // 5242880
            case 2048*100*16*8:  W2  = pp; break;   // 26214400
            case 2*20*16*16:     Wh1 = pp; break;   // 10240
            case 20*100*16*16:   Wh2 = pp; break;   // 512000
            case 1: if (!al1) al1 = pp; else al2 = pp; break;
        }
    }
    float* out = (float*)d_out;

    static int smem_set = 0;
    if (!smem_set) {
        cudaFuncSetAttribute(k_passB, cudaFuncAttributeMaxDynamicSharedMemorySize,
                             (16*100*16 + 16*100) * 4);
        smem_set = 1;
    }

    struct Lv { int C,Q,rep,repQ,h; const float *W,*Wh,*al; int off; };
    Lv L[3] = {
        {  2,  1,    1,    0, 0, W0, 0,   0,     0 },
        { 20,  2, 1024, 2048, 1, W1, Wh1, al1,  512 },
        {100, 20,  102, 2040, 1, W2, Wh2, al2, 5632 },
    };

    const float* prev = 0;
    for (int h = 0; h < 3; ++h) {
        Lv& v = L[h];
        k_zero<<<125, 256>>>();
        if (v.h) {
            int tot = 16*v.Q*v.C*16;
            k_hq<<<(tot+255)/256, 256>>>(v.Wh, prev, v.Q, v.C);
        }
        int CD = v.C*16;
        dim3 gA((CD+127)/128, 16);
        k_passA<<<gA, 128>>>(v.W, X, v.C);
        k_ws0<<<(16*v.C+255)/256, 256>>>(v.al, v.C, v.Q, v.rep, v.h);
        if (v.h) {
            int tot = 16*v.Q*v.C;
            k_hdoto<<<(tot+255)/256, 256>>>(v.Q, v.C);
        }
        size_t smB = (size_t)(16*v.C*16 + 16*v.C)*4;
        k_passB<<<NBLK_B, 256, smB>>>(v.W, X, v.al, v.C, v.Q, v.repQ, v.h);
        int tot = 16*v.C*16;
        k_reduce<<<(tot+255)/256, 256>>>(v.C);
        k_final<<<(16*v.C+255)/256, 256>>>(v.al, v.C, v.Q, v.h, out + v.off);
        prev = out + v.off;
    }
}

// round 3
// speedup vs baseline: 3.0961x; 3.0961x over previous
#include <cuda_runtime.h>
#include <math.h>

#define NP 2048

// Scratch (max-sized for level 2: C=100, Q=20)
__device__ __align__(16) float g_T0[16*100*16];
__device__ __align__(16) float g_WS1[16*100*16];
__device__ __align__(16) float g_R[16*20*100];
__device__ __align__(16) float g_HQ[16*20*100*16];
__device__ __align__(16) float g_HdotO[16*20*100];
__device__ __align__(16) float g_out0[16*100*16];
// partials: max(1024 * 16*20*16, 293 * 16*100*16) = 7,500,800 floats (~30 MB)
__device__ __align__(16) float g_WS1part[293 * 16*100*16];

// ws1 layout: [(d*C + c)*16 + b]  (conflict-free smem stores, coalesced flush)
#define WS_IDX(b,c,d,C) (((d)*(C) + (c))*16 + (b))

__device__ __forceinline__ float dot8(float4 w0, float4 w1, float4 xa, float4 xb) {
    return w0.x*xa.x + w0.y*xa.y + w0.z*xa.z + w0.w*xa.w
         + w1.x*xb.x + w1.y*xb.y + w1.z*xb.z + w1.w*xb.w;
}

__device__ __forceinline__ float sigmoidf(float x) {
    return 1.f / (1.f + __expf(-x));
}

__global__ void k_zero() {
    int i = blockIdx.x*256 + threadIdx.x;
    if (i < 16*100*16) { g_T0[i] = 0.f; g_WS1[i] = 0.f; }
    if (i < 16*20*100) g_R[i] = 0.f;
}

// HQ[b,q,c,d] = sum_e Wh[q,c,d,e] * prev[b,q,e]
__global__ void k_hq(const float* __restrict__ Wh, const float* __restrict__ prev,
                     int Q, int C) {
    int idx = blockIdx.x*256 + threadIdx.x;
    if (idx >= 16*Q*C*16) return;
    int d   = idx & 15;
    int rem = idx >> 4;          // (b*Q+q)*C + c
    int c   = rem % C;
    int bq  = rem / C;           // b*Q + q
    const float4* wh = (const float4*)(Wh + ((size_t)(((bq % Q)*C + c)*16 + d))*16);
    const float4* pv = (const float4*)(prev + (size_t)bq*16);
    float s = 0.f;
    #pragma unroll
    for (int e4 = 0; e4 < 4; ++e4) {
        float4 w = wh[e4], x = pv[e4];
        s += w.x*x.x + w.y*x.y + w.z*x.z + w.w*x.w;
    }
    g_HQ[idx] = s;
}

// T0[b,c,d] += sum_{p in 32-chunk, i} W[p,c,d,i] * X[b,p,i]
template<int C>
__global__ void __launch_bounds__(128)
k_passA(const float* __restrict__ W, const float* __restrict__ X) {
    constexpr int CD = C*16;
    __shared__ __align__(16) float xs[32*16*8];   // [p][b][i], 16 KB
    int t = threadIdx.x;
    int pBeg = blockIdx.y*32;
    for (int k = t; k < 32*16*8; k += 128) {
        int i  = k & 7;
        int bb = (k >> 3) & 15;
        int pp = k >> 7;
        xs[(pp*16 + bb)*8 + i] = X[((size_t)bb*NP + pBeg + pp)*8 + i];
    }
    __syncthreads();
    int cd = blockIdx.x*128 + t;
    if (cd >= CD) return;
    float acc[16];
    #pragma unroll
    for (int b = 0; b < 16; ++b) acc[b] = 0.f;
    for (int p = 0; p < 32; ++p) {
        const float4* wp = (const float4*)(W + ((size_t)(pBeg + p)*CD + cd)*8);
        float4 w0 = wp[0], w1 = wp[1];
        #pragma unroll
        for (int b = 0; b < 16; ++b) {
            const float4* xp = (const float4*)(xs + (p*16 + b)*8);
            acc[b] += dot8(w0, w1, xp[0], xp[1]);
        }
    }
    #pragma unroll
    for (int b = 0; b < 16; ++b) atomicAdd(&g_T0[b*CD + cd], acc[b]);
}

// out0[b,c,:] = squash( (a*T0 + (1-a)*rep*sum_q HQ) / C )
__global__ void k_ws0(const float* __restrict__ alpha, int C, int Q, int rep, int h) {
    int bc = blockIdx.x*256 + threadIdx.x;
    if (bc >= 16*C) return;
    int b = bc / C, c = bc % C;
    float a = 1.f, oma = 0.f;
    if (h) { a = sigmoidf(alpha[0]); oma = 1.f - a; }
    float invC = 1.f / (float)C;
    float v[16]; float sq = 0.f;
    #pragma unroll
    for (int d = 0; d < 16; ++d) {
        float t = a * g_T0[(b*C + c)*16 + d];
        if (h) {
            float hs = 0.f;
            for (int q = 0; q < Q; ++q) hs += g_HQ[((b*Q + q)*C + c)*16 + d];
            t += oma * (float)rep * hs;
        }
        t *= invC;
        v[d] = t; sq += t*t;
    }
    float sc = (sq/(1.f+sq)) * rsqrtf(sq + 1e-7f);
    #pragma unroll
    for (int d = 0; d < 16; ++d) g_out0[(b*C + c)*16 + d] = v[d]*sc;
}

// HdotO[b,q,c] = sum_d HQ[b,q,c,d] * out0[b,c,d]
__global__ void k_hdoto(int Q, int C) {
    int idx = blockIdx.x*256 + threadIdx.x;
    if (idx >= 16*Q*C) return;
    int c = idx % C;
    int b = (idx / C) / Q;
    const float* hq = g_HQ + (size_t)idx*16;
    const float* o  = g_out0 + (size_t)(b*C + c)*16;
    float s = 0.f;
    #pragma unroll
    for (int d = 0; d < 16; ++d) s += hq[d]*o[d];
    g_HdotO[idx] = s;
}

// Routing iteration 1 fused: raw -> softmax stats -> ws1 partial.
// predW cached in registers between phases; only (max, 1/sum) shared per b.
template<int C, int PB>
__global__ void __launch_bounds__(256)
k_passB(const float* __restrict__ W, const float* __restrict__ X,
        const float* __restrict__ alpha, int Q, int repQ, int h) {
    constexpr int NCMAX = (C + 15) / 16;
    constexpr int TOT = 16*C*16;
    extern __shared__ float sm[];
    float* ws1s = sm;               // TOT, WS_IDX layout
    float* rawS = sm + TOT;         // 16*C
    float* msS  = rawS + 16*C;      // 32
    int t = threadIdx.x;
    int b = t & 15, cB = t >> 4;
    float a = 1.f, oma = 0.f;
    if (h) { a = sigmoidf(alpha[0]); oma = 1.f - a; }
    for (int i = t; i < TOT; i += 256) ws1s[i] = 0.f;
    __syncthreads();

    float pw[NCMAX][16];
    float rl[NCMAX];

    int pBeg = blockIdx.x * PB;
    int pEnd = min(pBeg + PB, NP);
    for (int p = pBeg; p < pEnd; ++p) {
        const float4* xp = (const float4*)(X + ((size_t)b*NP + p)*8);
        float4 xa = xp[0], xb4 = xp[1];
        int q = p % Q;
        bool hv = h && (p < repQ);
        const float* Wp = W + (size_t)p*C*128;
        // phase 1: predW -> regs, raw -> smem (+local)
        #pragma unroll
        for (int ci = 0; ci < NCMAX; ++ci) {
            int c = cB + ci*16;
            if (c < C) {
                const float4* wc = (const float4*)(Wp + (size_t)c*128);
                const float4* ob = (const float4*)(g_out0 + (size_t)(b*C + c)*16);
                float r = 0.f;
                #pragma unroll
                for (int d4 = 0; d4 < 4; ++d4) {
                    float4 o = ob[d4];
                    float p0 = dot8(wc[d4*8+0], wc[d4*8+1], xa, xb4);
                    float p1 = dot8(wc[d4*8+2], wc[d4*8+3], xa, xb4);
                    float p2 = dot8(wc[d4*8+4], wc[d4*8+5], xa, xb4);
                    float p3 = dot8(wc[d4*8+6], wc[d4*8+7], xa, xb4);
                    pw[ci][d4*4+0] = p0; pw[ci][d4*4+1] = p1;
                    pw[ci][d4*4+2] = p2; pw[ci][d4*4+3] = p3;
                    r += p0*o.x + p1*o.y + p2*o.z + p3*o.w;
                }
                r *= a;
                if (hv) r += oma * g_HdotO[((size_t)(b*Q + q))*C + c];
                rl[ci] = r;
                rawS[b*C + c] = r;
            }
        }
        __syncthreads();
        // phase 2: per-b softmax stats (max, 1/sum); 16 lanes per b
        {
            int bS = t >> 4, j = t & 15;
            float m = -1e30f;
            for (int c = j; c < C; c += 16) m = fmaxf(m, rawS[bS*C + c]);
            #pragma unroll
            for (int k = 8; k; k >>= 1) m = fmaxf(m, __shfl_xor_sync(0xffffffffu, m, k));
            float s = 0.f;
            for (int c = j; c < C; c += 16) s += __expf(rawS[bS*C + c] - m);
            #pragma unroll
            for (int k = 8; k; k >>= 1) s += __shfl_xor_sync(0xffffffffu, s, k);
            if (j == 0) { msS[bS*2] = m; msS[bS*2+1] = 1.f / s; }
        }
        __syncthreads();
        // phase 3: ws1 += a*rw*predW (regs) ; R += rw
        float m  = msS[b*2];
        float is = msS[b*2+1];
        #pragma unroll
        for (int ci = 0; ci < NCMAX; ++ci) {
            int c = cB + ci*16;
            if (c < C) {
                float rw  = __expf(rl[ci] - m) * is;
                float arw = a * rw;
                #pragma unroll
                for (int d = 0; d < 16; ++d)
                    ws1s[WS_IDX(b,c,d,C)] += arw * pw[ci][d];
                if (hv) atomicAdd(&g_R[((size_t)(b*Q + q))*C + c], rw);
            }
        }
        // no barrier needed: next phase1 writes rawS (readers done pre-bar2),
        // next phase2 writes msS only after the next bar1.
    }
    __syncthreads();
    float* part = g_WS1part + (size_t)blockIdx.x * TOT;
    for (int i = t; i < TOT; i += 256) part[i] = ws1s[i];
}

// WS1[i] += sum over partials (float4 + 16-way split + atomic combine)
__global__ void k_reduce(int C, int nblk) {
    int tot = 16*C*16;
    int n4  = tot >> 2;
    int i4  = blockIdx.x*256 + threadIdx.x;
    if (i4 >= n4) return;
    const float4* base = (const float4*)g_WS1part;
    float4 s = make_float4(0.f, 0.f, 0.f, 0.f);
    for (int k = blockIdx.y; k < nblk; k += 16) {
        float4 v = base[(size_t)k*n4 + i4];
        s.x += v.x; s.y += v.y; s.z += v.z; s.w += v.w;
    }
    float* o = g_WS1 + (size_t)i4*4;
    atomicAdd(o+0, s.x); atomicAdd(o+1, s.y);
    atomicAdd(o+2, s.z); atomicAdd(o+3, s.w);
}

// out[b,c,:] = squash( WS1 + (1-a)*sum_q R[b,q,c]*HQ[b,q,c,:] )
__global__ void k_final(const float* __restrict__ alpha, int C, int Q, int h,
                        float* __restrict__ outp) {
    int bc = blockIdx.x*256 + threadIdx.x;
    if (bc >= 16*C) return;
    int b = bc / C, c = bc % C;
    float a = 1.f, oma = 0.f;
    if (h) { a = sigmoidf(alpha[0]); oma = 1.f - a; }
    float v[16]; float sq = 0.f;
    #pragma unroll
    for (int d = 0; d < 16; ++d) {
        float t = g_WS1[WS_IDX(b,c,d,C)];
        if (h) {
            float hs = 0.f;
            for (int q = 0; q < Q; ++q)
                hs += g_R[(b*Q + q)*C + c] * g_HQ[((b*Q + q)*C + c)*16 + d];
            t += oma * hs;
        }
        v[d] = t; sq += t*t;
    }
    float sc = (sq/(1.f+sq)) * rsqrtf(sq + 1e-7f);
    #pragma unroll
    for (int d = 0; d < 16; ++d) outp[(b*C + c)*16 + d] = v[d]*sc;
}

template<int C, int PB>
static void run_level(const float* W, const float* Wh, const float* al, const float* X,
                      const float* prev, int Q, int rep, int repQ, int h, float* outp) {
    constexpr int NBLK = (NP + PB - 1) / PB;
    constexpr int TOT  = 16*C*16;
    size_t smB = (size_t)(TOT + 16*C + 32) * 4;
    cudaFuncSetAttribute(k_passB<C,PB>, cudaFuncAttributeMaxDynamicSharedMemorySize, (int)smB);

    k_zero<<<125, 256>>>();
    if (h) {
        int tot = 16*Q*C*16;
        k_hq<<<(tot+255)/256, 256>>>(Wh, prev, Q, C);
    }
    constexpr int CD = C*16;
    dim3 gA((CD+127)/128, 64);
    k_passA<C><<<gA, 128>>>(W, X);
    k_ws0<<<(16*C+255)/256, 256>>>(al, C, Q, rep, h);
    if (h) {
        int tot = 16*Q*C;
        k_hdoto<<<(tot+255)/256, 256>>>(Q, C);
    }
    k_passB<C,PB><<<NBLK, 256, smB>>>(W, X, al, Q, repQ, h);
    int n4 = TOT >> 2;
    dim3 gR((n4+255)/256, 16);
    k_reduce<<<gR, 256>>>(C, NBLK);
    k_final<<<(16*C+255)/256, 256>>>(al, C, Q, h, outp);
}

extern "C" void kernel_launch(void* const* d_in, const int* in_sizes, int n_in,
                              void* d_out, int out_size) {
    const float *X=0,*W0=0,*W1=0,*W2=0,*Wh1=0,*Wh2=0,*al1=0,*al2=0;
    for (int i = 0; i < n_in; ++i) {
        const float* pp = (const float*)d_in[i];
        switch (in_sizes[i]) {
            case 16*2048*8:      X   = pp; break;
            case 2048*2*16*8:    W0  = pp; break;
            case 2048*20*16*8:   W1  = pp; break;
            case 2048*100*16*8:  W2  = pp; break;
            case 2*20*16*16:     Wh1 = pp; break;
            case 20*100*16*16:   Wh2 = pp; break;
            case 1: if (!al1) al1 = pp; else al2 = pp; break;
        }
    }
    float* out = (float*)d_out;

    run_level<2,2>  (W0, 0,   0,   X, 0,          1,    1,    0, 0, out + 0);
    run_level<20,2> (W1, Wh1, al1, X, out + 0,    2, 1024, 2048, 1, out + 512);
    run_level<100,7>(W2, Wh2, al2, X, out + 512, 20,  102, 2040, 1, out + 5632);
}